// round 4
// baseline (speedup 1.0000x reference)
#include <cuda_runtime.h>
#include <cstdint>
#include <cstddef>

// ---------------- constants ----------------
#define BATCH   16
#define TOK     4096
#define HID     1152
#define QKVN    3456
#define MLPN    4608
#define ADAN    6912
#define DH      72

// ---------------- scratch ----------------
__device__ float g_h  [TOK * HID];
__device__ float g_x1 [TOK * HID];
__device__ float g_qkv[TOK * QKVN];
__device__ float g_ao [TOK * HID];
__device__ float g_mh [TOK * MLPN];
__device__ float g_e1 [BATCH * HID];
__device__ float g_scb[BATCH * HID];
__device__ float g_mod [BATCH * ADAN];
__device__ float g_fmod[BATCH * 2304];

// ---------------- helpers ----------------
__device__ __forceinline__ float silu_f(float x) { return x / (1.f + expf(-x)); }
__device__ __forceinline__ float gelu_f(float x) {
    float x3 = x * x * x;
    return 0.5f * x * (1.f + tanhf(0.7978845608028654f * (x + 0.044715f * x3)));
}
__device__ __forceinline__ float tf32r(float x) {
    float r;
    asm("cvt.rna.tf32.f32 %0, %1;" : "=f"(r) : "f"(x));
    return r;
}
__device__ __forceinline__ uint32_t su32(const void* p) {
    uint32_t a;
    asm("{ .reg .u64 t; cvta.to.shared.u64 t, %1; cvt.u32.u64 %0, t; }" : "=r"(a) : "l"(p));
    return a;
}
__device__ __forceinline__ void cpa16(uint32_t dst, const float* src) {
    asm volatile("cp.async.cg.shared.global [%0], [%1], 16;" :: "r"(dst), "l"(src) : "memory");
}
__device__ __forceinline__ void cpa_commit() {
    asm volatile("cp.async.commit_group;" ::: "memory");
}
__device__ __forceinline__ void mma8(float* d, const float* a, const float* b) {
    asm volatile("mma.sync.aligned.m16n8k8.row.col.f32.tf32.tf32.f32 "
                 "{%0,%1,%2,%3}, {%4,%5,%6,%7}, {%8,%9}, {%0,%1,%2,%3};"
                 : "+f"(d[0]), "+f"(d[1]), "+f"(d[2]), "+f"(d[3])
                 : "r"(__float_as_uint(a[0])), "r"(__float_as_uint(a[1])),
                   "r"(__float_as_uint(a[2])), "r"(__float_as_uint(a[3])),
                   "r"(__float_as_uint(b[0])), "r"(__float_as_uint(b[1])));
}

// ---------------- tf32 mma.sync GEMM: C[4096 x N] = A[4096 x K] * W[K x N] ----------------
// A rows already tf32-rounded by producers; B cvt'd in-register.
// EPI 0: C = acc + bias ; EPI 1: C = tf32(gelu(acc+bias)) ; EPI 2: C += gate[b][n]*(acc+bias)
// smem: As 2 x [128][36] (k-major), Bs 2 x [32][132] (n-major rows)
#define GSME 70656

template<int EPI>
__global__ void __launch_bounds__(256, 2) mma_gemm(
    const float* __restrict__ A, const float* __restrict__ W,
    const float* __restrict__ bias, float* __restrict__ C,
    const float* __restrict__ gate, int gstride, int N, int K)
{
    extern __shared__ float sm[];
    float* As = sm;                   // 2*128*36 = 9216
    float* Bs = sm + 9216;            // 2*32*132 = 8448
    uint32_t smB = su32(sm);

    int tid = threadIdx.x;
    int m0 = blockIdx.y * 128, n0 = blockIdx.x * 128;
    int lane = tid & 31, wid = tid >> 5;
    int wm = wid >> 2, wn = wid & 3;
    int g = lane >> 2, q = lane & 3;

    const float* Abase = A + (size_t)m0 * K;
    const float* Wbase = W + n0;

    const int NC = K >> 5;
    float acc[4][4][4];
#pragma unroll
    for (int i = 0; i < 4; i++)
#pragma unroll
        for (int j = 0; j < 4; j++)
#pragma unroll
            for (int r = 0; r < 4; r++) acc[i][j][r] = 0.f;

    // prefetch chunk 0 into buf 0
    {
#pragma unroll
        for (int i = 0; i < 4; i++) {
            int idx = tid + i * 256;
            int ar = idx >> 3, ac4 = (idx & 7) * 4;
            cpa16(smB + (uint32_t)((ar * 36 + ac4) * 4), Abase + (size_t)ar * K + ac4);
            int bk = idx >> 5, bc4 = (idx & 31) * 4;
            cpa16(smB + (uint32_t)((9216 + bk * 132 + bc4) * 4), Wbase + (size_t)bk * N + bc4);
        }
        cpa_commit();
    }

    for (int c = 0; c < NC; c++) {
        int buf = c & 1;
        if (c + 1 < NC) {
            int nb = buf ^ 1;
            const float* Ab = Abase + (c + 1) * 32;
            const float* Wb = Wbase + (size_t)((c + 1) * 32) * N;
#pragma unroll
            for (int i = 0; i < 4; i++) {
                int idx = tid + i * 256;
                int ar = idx >> 3, ac4 = (idx & 7) * 4;
                cpa16(smB + (uint32_t)((nb * 4608 + ar * 36 + ac4) * 4), Ab + (size_t)ar * K + ac4);
                int bk = idx >> 5, bc4 = (idx & 31) * 4;
                cpa16(smB + (uint32_t)((9216 + nb * 4224 + bk * 132 + bc4) * 4), Wb + (size_t)bk * N + bc4);
            }
            cpa_commit();
            asm volatile("cp.async.wait_group 1;" ::: "memory");
        } else {
            asm volatile("cp.async.wait_group 0;" ::: "memory");
        }
        __syncthreads();

        const float* Abuf = As + buf * 4608 + (wm * 64 + g) * 36;
        const float* Bbuf = Bs + buf * 4224;
        int ncol = wn * 32 + g;
#pragma unroll
        for (int ks = 0; ks < 4; ks++) {
            int ko = ks * 8 + q;
            float a[4][4], b[4][2];
#pragma unroll
            for (int mi = 0; mi < 4; mi++) {
                const float* p = Abuf + mi * 16 * 36 + ko;
                a[mi][0] = p[0];
                a[mi][1] = p[8 * 36];
                a[mi][2] = p[4];
                a[mi][3] = p[8 * 36 + 4];
            }
            const float* pb0 = Bbuf + ko * 132 + ncol;
            const float* pb1 = Bbuf + (ko + 4) * 132 + ncol;
#pragma unroll
            for (int ni = 0; ni < 4; ni++) {
                b[ni][0] = tf32r(pb0[ni * 8]);
                b[ni][1] = tf32r(pb1[ni * 8]);
            }
#pragma unroll
            for (int mi = 0; mi < 4; mi++)
#pragma unroll
                for (int ni = 0; ni < 4; ni++)
                    mma8(acc[mi][ni], a[mi], b[ni]);
        }
        __syncthreads();
    }

    // ---- epilogue ----
    int bidx = m0 >> 8;
#pragma unroll
    for (int mi = 0; mi < 4; mi++) {
#pragma unroll
        for (int half = 0; half < 2; half++) {
            int row = m0 + wm * 64 + mi * 16 + g + half * 8;
            float* Crow = C + (size_t)row * N;
#pragma unroll
            for (int ni = 0; ni < 4; ni++) {
                int col = n0 + wn * 32 + ni * 8 + 2 * q;
                float2 bv = *(const float2*)(bias + col);
                float v0 = acc[mi][ni][half * 2 + 0] + bv.x;
                float v1 = acc[mi][ni][half * 2 + 1] + bv.y;
                if (EPI == 1) { v0 = tf32r(gelu_f(v0)); v1 = tf32r(gelu_f(v1)); }
                if (EPI == 2) {
                    float2 gv = *(const float2*)(gate + (size_t)bidx * gstride + col);
                    float2 cv = *(float2*)(Crow + col);
                    cv.x += gv.x * v0; cv.y += gv.y * v1;
                    *(float2*)(Crow + col) = cv;
                } else {
                    float2 ov = make_float2(v0, v1);
                    *(float2*)(Crow + col) = ov;
                }
            }
        }
    }
}

// ---------------- bicubic ----------------
__device__ __forceinline__ void bicubic_w(int i, float w[4]) {
    float s = (i + 0.5f) * 0.25f - 0.5f;
    float tot = 0.f;
#pragma unroll
    for (int j = 0; j < 4; j++) {
        float x = fabsf(s - (float)j);
        float v;
        if (x >= 2.f)      v = 0.f;
        else if (x >= 1.f) v = ((-0.5f * x + 2.5f) * x - 4.f) * x + 2.f;
        else               v = ((1.5f * x - 2.5f) * x) * x + 1.f;
        w[j] = v; tot += v;
    }
    float inv = 1.f / tot;
#pragma unroll
    for (int j = 0; j < 4; j++) w[j] *= inv;
}

// ---------------- patchify + pos-embed ----------------
__global__ void __launch_bounds__(288) patchify_kernel(
    const float* __restrict__ x, const float* __restrict__ pw,
    const float* __restrict__ pb, const float* __restrict__ pe)
{
    int t = blockIdx.x;
    int b = t >> 8, gy = (t >> 4) & 15, gx = t & 15;

    float xr[16];
#pragma unroll
    for (int ic = 0; ic < 4; ic++)
#pragma unroll
        for (int py = 0; py < 2; py++)
#pragma unroll
            for (int px = 0; px < 2; px++)
                xr[ic * 4 + py * 2 + px] =
                    x[(((size_t)b * 4 + ic) * 32 + (gy * 2 + py)) * 32 + gx * 2 + px];

    float wy[4], wx[4];
    bicubic_w(gy, wy); bicubic_w(gx, wx);
    float wyx[16];
#pragma unroll
    for (int jy = 0; jy < 4; jy++)
#pragma unroll
        for (int jx = 0; jx < 4; jx++) wyx[jy * 4 + jx] = wy[jy] * wx[jx];

    for (int o = threadIdx.x; o < HID; o += 288) {
        float a = pb[o];
        const float* w = pw + (size_t)o * 16;
#pragma unroll
        for (int qq = 0; qq < 16; qq++) a += xr[qq] * w[qq];
        float p = 0.f;
#pragma unroll
        for (int qq = 0; qq < 16; qq++) p += wyx[qq] * pe[(size_t)qq * HID + o];
        g_h[(size_t)t * HID + o] = a + p;
    }
}

// ---------------- timestep embedding (all batches per block) ----------------
__global__ void __launch_bounds__(128) temb1_kernel(
    const float* __restrict__ tin, const float* __restrict__ w1, const float* __restrict__ b1)
{
    __shared__ float te[BATCH * 256];
    int tid = threadIdx.x;
    for (int i = tid; i < BATCH * 256; i += 128) {
        int b = i >> 8, k = i & 255;
        float fr = expf(-9.210340371976184f * (float)(k & 127) / 128.f);
        float arg = tin[b] * fr;
        te[i] = (k < 128) ? cosf(arg) : sinf(arg);
    }
    __syncthreads();
    int j = blockIdx.x * 128 + tid;
    float acc[BATCH];
    float bj = b1[j];
#pragma unroll
    for (int b = 0; b < BATCH; b++) acc[b] = bj;
    for (int k = 0; k < 256; k++) {
        float wv = w1[(size_t)k * HID + j];
#pragma unroll
        for (int b = 0; b < BATCH; b++) acc[b] = fmaf(te[b * 256 + k], wv, acc[b]);
    }
#pragma unroll
    for (int b = 0; b < BATCH; b++) g_e1[b * HID + j] = silu_f(acc[b]);
}

__global__ void __launch_bounds__(128) temb2_kernel(
    const float* __restrict__ w2, const float* __restrict__ b2,
    const float* __restrict__ ytab, const int* __restrict__ y)
{
    extern __shared__ float e[];     // BATCH * HID
    int tid = threadIdx.x;
    for (int i = tid; i < BATCH * HID; i += 128) e[i] = g_e1[i];
    __syncthreads();
    int j = blockIdx.x * 128 + tid;
    float acc[BATCH];
    float bj = b2[j];
#pragma unroll
    for (int b = 0; b < BATCH; b++) acc[b] = bj;
    for (int k = 0; k < HID; k++) {
        float wv = w2[(size_t)k * HID + j];
#pragma unroll
        for (int b = 0; b < BATCH; b++) acc[b] = fmaf(e[b * HID + k], wv, acc[b]);
    }
#pragma unroll
    for (int b = 0; b < BATCH; b++) {
        float cv = acc[b] + ytab[(size_t)y[b] * HID + j];
        g_scb[b * HID + j] = silu_f(cv);
    }
}

// ---------------- conditioning GEMM (all batches per block) ----------------
__global__ void __launch_bounds__(128) modk_kernel(
    const float* __restrict__ W, const float* __restrict__ bias,
    float* __restrict__ out, int Nout)
{
    extern __shared__ float s[];     // BATCH * HID
    int tid = threadIdx.x;
    for (int i = tid; i < BATCH * HID; i += 128) s[i] = g_scb[i];
    __syncthreads();
    int j = blockIdx.x * 128 + tid;
    float acc[BATCH];
    float bj = bias[j];
#pragma unroll
    for (int b = 0; b < BATCH; b++) acc[b] = bj;
    for (int k = 0; k < HID; k += 2) {
        float wv0 = W[(size_t)k * Nout + j];
        float wv1 = W[(size_t)(k + 1) * Nout + j];
#pragma unroll
        for (int b = 0; b < BATCH; b++) {
            float2 sv = *(const float2*)&s[b * HID + k];
            acc[b] = fmaf(sv.x, wv0, acc[b]);
            acc[b] = fmaf(sv.y, wv1, acc[b]);
        }
    }
#pragma unroll
    for (int b = 0; b < BATCH; b++) out[(size_t)b * Nout + j] = acc[b];
}

// ---------------- LN + adaLN modulate (tf32-rounded output) ----------------
__global__ void __launch_bounds__(288) ln_mod_kernel(
    const float* __restrict__ sh, const float* __restrict__ sc, int mstride)
{
    int t = blockIdx.x;
    int b = t >> 8;
    int tid = threadIdx.x;
    const float* row = g_h + (size_t)t * HID;
    float v[4]; float s = 0.f, s2 = 0.f;
#pragma unroll
    for (int k = 0; k < 4; k++) {
        float xv = row[tid + k * 288];
        v[k] = xv; s += xv; s2 += xv * xv;
    }
#pragma unroll
    for (int o = 16; o > 0; o >>= 1) {
        s  += __shfl_xor_sync(0xffffffffu, s, o);
        s2 += __shfl_xor_sync(0xffffffffu, s2, o);
    }
    __shared__ float ws[9], ws2[9];
    int w = tid >> 5, lane = tid & 31;
    if (lane == 0) { ws[w] = s; ws2[w] = s2; }
    __syncthreads();
    if (tid == 0) {
        float a = 0.f, a2 = 0.f;
        for (int i = 0; i < 9; i++) { a += ws[i]; a2 += ws2[i]; }
        ws[0] = a; ws2[0] = a2;
    }
    __syncthreads();
    float mean = ws[0] * (1.f / HID);
    float var  = ws2[0] * (1.f / HID) - mean * mean;
    float rstd = rsqrtf(var + 1e-6f);
    const float* shr = sh + (size_t)b * mstride;
    const float* scr = sc + (size_t)b * mstride;
    float* orow = g_x1 + (size_t)t * HID;
#pragma unroll
    for (int k = 0; k < 4; k++) {
        int j = tid + k * 288;
        float xm = (v[k] - mean) * rstd;
        orow[j] = tf32r(xm * (1.f + scr[j]) + shr[j]);
    }
}

// ---------------- neighborhood attention (tf32-rounded output) ----------------
__global__ void __launch_bounds__(256) attn_kernel()
{
    int t = blockIdx.x;
    int b = t >> 8, i = (t >> 4) & 15, j = t & 15;
    int tid = threadIdx.x;
    int h = tid >> 4, p = tid & 15;

    __shared__ int   ntok[16];
    __shared__ float att[16][16];

    if (tid < 16) {
        int py = tid >> 2, px = tid & 3;
        int si = min(max(i - 2, 0), 12);
        int sj = min(max(j - 2, 0), 12);
        ntok[tid] = (b << 8) | ((si + py) << 4) | (sj + px);
    }
    __syncthreads();

    const float* qrow = g_qkv + (size_t)t * QKVN + h * DH;
    const float* krow = g_qkv + (size_t)ntok[p] * QKVN + HID + h * DH;
    float acc = 0.f;
#pragma unroll 8
    for (int d = 0; d < DH; d++) acc += qrow[d] * krow[d];
    acc *= 0.11785113019775793f;

    float m = acc;
#pragma unroll
    for (int o = 8; o > 0; o >>= 1) m = fmaxf(m, __shfl_xor_sync(0xffffffffu, m, o, 16));
    float e = expf(acc - m);
    float s = e;
#pragma unroll
    for (int o = 8; o > 0; o >>= 1) s += __shfl_xor_sync(0xffffffffu, s, o, 16);
    att[h][p] = e / s;
    __syncthreads();

    for (int o = tid; o < HID; o += 256) {
        int hh = o / DH;
        float sum = 0.f;
#pragma unroll
        for (int p2 = 0; p2 < 16; p2++)
            sum += att[hh][p2] * g_qkv[(size_t)ntok[p2] * QKVN + 2304 + o];
        g_ao[(size_t)t * HID + o] = tf32r(sum);
    }
}

// ---------------- final linear + unpatchify ----------------
__global__ void __launch_bounds__(256) final_kernel(
    const float* __restrict__ flw, const float* __restrict__ flb, float* __restrict__ out)
{
    int t = blockIdx.x;
    int b = t >> 8, gy = (t >> 4) & 15, gx = t & 15;
    __shared__ float xs[HID];
    __shared__ float part[8][32];
    int tid = threadIdx.x;
    for (int k = tid; k < HID; k += 256) xs[k] = g_x1[(size_t)t * HID + k];
    __syncthreads();
    int col = tid & 31, seg = tid >> 5;
    float acc = 0.f;
    int k0 = seg * 144;
    for (int k = k0; k < k0 + 144; k++)
        acc += xs[k] * flw[(size_t)k * 32 + col];
    part[seg][col] = acc;
    __syncthreads();
    if (tid < 32) {
        float s = flb[tid];
#pragma unroll
        for (int sg = 0; sg < 8; sg++) s += part[sg][tid];
        int ch = tid & 7, pq = tid >> 3, p = pq >> 1, q = pq & 1;
        out[(((size_t)b * 8 + ch) * 32 + gy * 2 + p) * 32 + gx * 2 + q] = s;
    }
}

// ---------------- launch ----------------
extern "C" void kernel_launch(void* const* d_in, const int* in_sizes, int n_in,
                              void* d_out, int out_size)
{
    const float* x    = (const float*)d_in[0];
    const float* tin  = (const float*)d_in[1];
    const int*   y    = (const int*)  d_in[2];
    const float* pos  = (const float*)d_in[3];
    const float* pw   = (const float*)d_in[4];
    const float* pb   = (const float*)d_in[5];
    const float* tw1  = (const float*)d_in[6];
    const float* tb1  = (const float*)d_in[7];
    const float* tw2  = (const float*)d_in[8];
    const float* tb2  = (const float*)d_in[9];
    const float* ytab = (const float*)d_in[10];
    const float* adaw = (const float*)d_in[11];
    const float* adab = (const float*)d_in[12];
    const float* qkvw = (const float*)d_in[13];
    const float* qkvb = (const float*)d_in[14];
    const float* prjw = (const float*)d_in[15];
    const float* prjb = (const float*)d_in[16];
    const float* m1w  = (const float*)d_in[17];
    const float* m1b  = (const float*)d_in[18];
    const float* m2w  = (const float*)d_in[19];
    const float* m2b  = (const float*)d_in[20];
    const float* flaw = (const float*)d_in[21];
    const float* flab = (const float*)d_in[22];
    const float* flw  = (const float*)d_in[23];
    const float* flb  = (const float*)d_in[24];
    float* out = (float*)d_out;

    float *p_x1, *p_qkv, *p_ao, *p_mh, *p_h, *p_mod, *p_fmod;
    cudaGetSymbolAddress((void**)&p_x1,  g_x1);
    cudaGetSymbolAddress((void**)&p_qkv, g_qkv);
    cudaGetSymbolAddress((void**)&p_ao,  g_ao);
    cudaGetSymbolAddress((void**)&p_mh,  g_mh);
    cudaGetSymbolAddress((void**)&p_h,   g_h);
    cudaGetSymbolAddress((void**)&p_mod, g_mod);
    cudaGetSymbolAddress((void**)&p_fmod, g_fmod);

    const int CSME = BATCH * HID * 4;   // 73728
    cudaFuncSetAttribute(mma_gemm<0>, cudaFuncAttributeMaxDynamicSharedMemorySize, GSME);
    cudaFuncSetAttribute(mma_gemm<1>, cudaFuncAttributeMaxDynamicSharedMemorySize, GSME);
    cudaFuncSetAttribute(mma_gemm<2>, cudaFuncAttributeMaxDynamicSharedMemorySize, GSME);
    cudaFuncSetAttribute(modk_kernel, cudaFuncAttributeMaxDynamicSharedMemorySize, CSME);
    cudaFuncSetAttribute(temb2_kernel, cudaFuncAttributeMaxDynamicSharedMemorySize, CSME);

    patchify_kernel<<<TOK, 288>>>(x, pw, pb, pos);
    temb1_kernel<<<HID / 128, 128>>>(tin, tw1, tb1);
    temb2_kernel<<<HID / 128, 128, CSME>>>(tw2, tb2, ytab, y);

    for (int l = 0; l < 2; l++) {
        const float* aw = adaw + (size_t)l * HID * ADAN;
        const float* ab = adab + (size_t)l * ADAN;
        modk_kernel<<<ADAN / 128, 128, CSME>>>(aw, ab, p_mod, ADAN);

        // attention block
        ln_mod_kernel<<<TOK, 288>>>(p_mod + 0, p_mod + HID, ADAN);
        mma_gemm<0><<<dim3(QKVN / 128, TOK / 128), 256, GSME>>>(
            p_x1, qkvw + (size_t)l * HID * QKVN, qkvb + (size_t)l * QKVN,
            p_qkv, nullptr, 0, QKVN, HID);
        attn_kernel<<<TOK, 256>>>();
        mma_gemm<2><<<dim3(HID / 128, TOK / 128), 256, GSME>>>(
            p_ao, prjw + (size_t)l * HID * HID, prjb + (size_t)l * HID,
            p_h, p_mod + 2 * HID, ADAN, HID, HID);

        // mlp block
        ln_mod_kernel<<<TOK, 288>>>(p_mod + 3 * HID, p_mod + 4 * HID, ADAN);
        mma_gemm<1><<<dim3(MLPN / 128, TOK / 128), 256, GSME>>>(
            p_x1, m1w + (size_t)l * HID * MLPN, m1b + (size_t)l * MLPN,
            p_mh, nullptr, 0, MLPN, HID);
        mma_gemm<2><<<dim3(HID / 128, TOK / 128), 256, GSME>>>(
            p_mh, m2w + (size_t)l * MLPN * HID, m2b + (size_t)l * HID,
            p_h, p_mod + 5 * HID, ADAN, HID, MLPN);
    }

    modk_kernel<<<2304 / 128, 128, CSME>>>(flaw, flab, p_fmod, 2304);
    ln_mod_kernel<<<TOK, 288>>>(p_fmod + 0, p_fmod + HID, 2304);
    final_kernel<<<TOK, 256>>>(flw, flb, out);

    (void)in_sizes; (void)n_in; (void)out_size;
}

// round 5
// speedup vs baseline: 1.5201x; 1.5201x over previous
#include <cuda_runtime.h>
#include <cstdint>
#include <cstddef>

// ---------------- constants ----------------
#define BATCH   16
#define TOK     4096
#define HID     1152
#define QKVN    3456
#define MLPN    4608
#define ADAN    6912
#define DH      72

// ---------------- scratch ----------------
__device__ float g_h  [TOK * HID];
__device__ float g_x1 [TOK * HID];
__device__ float g_qkv[TOK * QKVN];
__device__ float g_ao [TOK * HID];
__device__ float g_mh [TOK * MLPN];
__device__ float g_te [BATCH * 256];
__device__ float g_e1 [BATCH * HID];
__device__ float g_scb[BATCH * HID];
__device__ float g_mod [BATCH * ADAN];
__device__ float g_fmod[BATCH * 2304];
__device__ float g_part[9 * BATCH * ADAN];   // split-K partials (max KS=9, N=6912)

// ---------------- helpers ----------------
__device__ __forceinline__ float silu_f(float x) { return x / (1.f + expf(-x)); }
__device__ __forceinline__ float gelu_f(float x) {
    float x3 = x * x * x;
    return 0.5f * x * (1.f + tanhf(0.7978845608028654f * (x + 0.044715f * x3)));
}
__device__ __forceinline__ float tf32r(float x) {
    float r;
    asm("cvt.rna.tf32.f32 %0, %1;" : "=f"(r) : "f"(x));
    return r;
}
__device__ __forceinline__ uint32_t su32(const void* p) {
    uint32_t a;
    asm("{ .reg .u64 t; cvta.to.shared.u64 t, %1; cvt.u32.u64 %0, t; }" : "=r"(a) : "l"(p));
    return a;
}
__device__ __forceinline__ void cpa16(uint32_t dst, const float* src) {
    asm volatile("cp.async.cg.shared.global [%0], [%1], 16;" :: "r"(dst), "l"(src) : "memory");
}
__device__ __forceinline__ void cpa_commit() {
    asm volatile("cp.async.commit_group;" ::: "memory");
}
__device__ __forceinline__ void mma8(float* d, const float* a, const float* b) {
    asm volatile("mma.sync.aligned.m16n8k8.row.col.f32.tf32.tf32.f32 "
                 "{%0,%1,%2,%3}, {%4,%5,%6,%7}, {%8,%9}, {%0,%1,%2,%3};"
                 : "+f"(d[0]), "+f"(d[1]), "+f"(d[2]), "+f"(d[3])
                 : "r"(__float_as_uint(a[0])), "r"(__float_as_uint(a[1])),
                   "r"(__float_as_uint(a[2])), "r"(__float_as_uint(a[3])),
                   "r"(__float_as_uint(b[0])), "r"(__float_as_uint(b[1])));
}

// ---------------- tf32 mma.sync GEMM: C[4096 x N] = A[4096 x K] * W[K x N] ----------------
// A rows tf32-rounded by producers; B raw fp32 bits read as tf32 (truncation).
// EPI 0: C = acc + bias ; EPI 1: C = tf32(gelu(acc+bias)) ; EPI 2: C += gate[b][n]*(acc+bias)
// smem: As 2 x [128][36] (k-major), Bs 2 x [32][136] (n-major rows, conflict-free)
#define GSME 71680

template<int EPI>
__global__ void __launch_bounds__(256, 2) mma_gemm(
    const float* __restrict__ A, const float* __restrict__ W,
    const float* __restrict__ bias, float* __restrict__ C,
    const float* __restrict__ gate, int gstride, int N, int K)
{
    extern __shared__ float sm[];
    float* As = sm;                   // 2*128*36 = 9216
    float* Bs = sm + 9216;            // 2*32*136 = 8704
    uint32_t smB = su32(sm);

    int tid = threadIdx.x;
    int m0 = blockIdx.y * 128, n0 = blockIdx.x * 128;
    int lane = tid & 31, wid = tid >> 5;
    int wm = wid >> 2, wn = wid & 3;
    int g = lane >> 2, q = lane & 3;

    const float* Abase = A + (size_t)m0 * K;
    const float* Wbase = W + n0;

    const int NC = K >> 5;
    float acc[4][4][4];
#pragma unroll
    for (int i = 0; i < 4; i++)
#pragma unroll
        for (int j = 0; j < 4; j++)
#pragma unroll
            for (int r = 0; r < 4; r++) acc[i][j][r] = 0.f;

    // prefetch chunk 0 into buf 0
    {
#pragma unroll
        for (int i = 0; i < 4; i++) {
            int idx = tid + i * 256;
            int ar = idx >> 3, ac4 = (idx & 7) * 4;
            cpa16(smB + (uint32_t)((ar * 36 + ac4) * 4), Abase + (size_t)ar * K + ac4);
            int bk = idx >> 5, bc4 = (idx & 31) * 4;
            cpa16(smB + (uint32_t)((9216 + bk * 136 + bc4) * 4), Wbase + (size_t)bk * N + bc4);
        }
        cpa_commit();
    }

    for (int c = 0; c < NC; c++) {
        int buf = c & 1;
        if (c + 1 < NC) {
            int nb = buf ^ 1;
            const float* Ab = Abase + (c + 1) * 32;
            const float* Wb = Wbase + (size_t)((c + 1) * 32) * N;
#pragma unroll
            for (int i = 0; i < 4; i++) {
                int idx = tid + i * 256;
                int ar = idx >> 3, ac4 = (idx & 7) * 4;
                cpa16(smB + (uint32_t)((nb * 4608 + ar * 36 + ac4) * 4), Ab + (size_t)ar * K + ac4);
                int bk = idx >> 5, bc4 = (idx & 31) * 4;
                cpa16(smB + (uint32_t)((9216 + nb * 4352 + bk * 136 + bc4) * 4), Wb + (size_t)bk * N + bc4);
            }
            cpa_commit();
            asm volatile("cp.async.wait_group 1;" ::: "memory");
        } else {
            asm volatile("cp.async.wait_group 0;" ::: "memory");
        }
        __syncthreads();

        const float* Abuf = As + buf * 4608 + (wm * 64 + g) * 36;
        const float* Bbuf = Bs + buf * 4352;
        int ncol = wn * 32 + g;
#pragma unroll
        for (int ks = 0; ks < 4; ks++) {
            int ko = ks * 8 + q;
            float a[4][4], b[4][2];
#pragma unroll
            for (int mi = 0; mi < 4; mi++) {
                const float* p = Abuf + mi * 16 * 36 + ko;
                a[mi][0] = p[0];
                a[mi][1] = p[8 * 36];
                a[mi][2] = p[4];
                a[mi][3] = p[8 * 36 + 4];
            }
            const float* pb0 = Bbuf + ko * 136 + ncol;
            const float* pb1 = Bbuf + (ko + 4) * 136 + ncol;
#pragma unroll
            for (int ni = 0; ni < 4; ni++) {
                b[ni][0] = pb0[ni * 8];
                b[ni][1] = pb1[ni * 8];
            }
#pragma unroll
            for (int mi = 0; mi < 4; mi++)
#pragma unroll
                for (int ni = 0; ni < 4; ni++)
                    mma8(acc[mi][ni], a[mi], b[ni]);
        }
        __syncthreads();
    }

    // ---- epilogue ----
    int bidx = m0 >> 8;
#pragma unroll
    for (int mi = 0; mi < 4; mi++) {
#pragma unroll
        for (int half = 0; half < 2; half++) {
            int row = m0 + wm * 64 + mi * 16 + g + half * 8;
            float* Crow = C + (size_t)row * N;
#pragma unroll
            for (int ni = 0; ni < 4; ni++) {
                int col = n0 + wn * 32 + ni * 8 + 2 * q;
                float2 bv = *(const float2*)(bias + col);
                float v0 = acc[mi][ni][half * 2 + 0] + bv.x;
                float v1 = acc[mi][ni][half * 2 + 1] + bv.y;
                if (EPI == 1) { v0 = tf32r(gelu_f(v0)); v1 = tf32r(gelu_f(v1)); }
                if (EPI == 2) {
                    float2 gv = *(const float2*)(gate + (size_t)bidx * gstride + col);
                    float2 cv = *(float2*)(Crow + col);
                    cv.x += gv.x * v0; cv.y += gv.y * v1;
                    *(float2*)(Crow + col) = cv;
                } else {
                    float2 ov = make_float2(v0, v1);
                    *(float2*)(Crow + col) = ov;
                }
            }
        }
    }
}

// ---------------- conditioning path: split-K small-M GEMM ----------------
// partials: g_part[(kz*BATCH + b)*N + j] = sum_{k in chunk} A[b][k] * W[k][j]
__global__ void __launch_bounds__(128) smk_part(
    const float* __restrict__ Abuf, const float* __restrict__ W, int N)
{
    __shared__ float s[BATCH * 128];
    int tid = threadIdx.x;
    int kz = blockIdx.y;
    int j = blockIdx.x * 128 + tid;
    for (int i = tid; i < BATCH * 128; i += 128) {
        int b = i >> 7, kk = i & 127;
        s[b * 128 + kk] = Abuf[b * ((int)gridDim.y * 128) + kz * 128 + kk];
    }
    __syncthreads();
    float acc[BATCH];
#pragma unroll
    for (int b = 0; b < BATCH; b++) acc[b] = 0.f;
    const float* Wp = W + (size_t)(kz * 128) * N + j;
#pragma unroll 4
    for (int kk = 0; kk < 128; kk++) {
        float wv = Wp[(size_t)kk * N];
#pragma unroll
        for (int b = 0; b < BATCH; b++) acc[b] = fmaf(s[b * 128 + kk], wv, acc[b]);
    }
#pragma unroll
    for (int b = 0; b < BATCH; b++)
        g_part[(size_t)(kz * BATCH + b) * N + j] = acc[b];
}

// EPI 0: out = sum + bias            (adaLN mod vectors)
// EPI 1: out = silu(sum + bias)      (temb1 -> g_e1)
// EPI 2: out = silu(sum + bias + ytab[y[b]][j])   (temb2 -> g_scb)
template<int EPI>
__global__ void __launch_bounds__(128) smk_reduce(
    const float* __restrict__ bias, const float* __restrict__ ytab,
    const int* __restrict__ y, float* __restrict__ out, int N, int KS)
{
    int j = blockIdx.x * 128 + threadIdx.x;
    float bj = bias[j];
#pragma unroll 4
    for (int b = 0; b < BATCH; b++) {
        float acc = bj;
        for (int kz = 0; kz < KS; kz++)
            acc += g_part[(size_t)(kz * BATCH + b) * N + j];
        if (EPI == 1) acc = silu_f(acc);
        if (EPI == 2) acc = silu_f(acc + ytab[(size_t)y[b] * HID + j]);
        out[(size_t)b * N + j] = acc;
    }
}

// timestep sinusoid table
__global__ void __launch_bounds__(256) te_kernel(const float* __restrict__ tin)
{
    int b = blockIdx.x, k = threadIdx.x;
    float fr = expf(-9.210340371976184f * (float)(k & 127) / 128.f);
    float arg = tin[b] * fr;
    g_te[b * 256 + k] = (k < 128) ? cosf(arg) : sinf(arg);
}

// ---------------- bicubic ----------------
__device__ __forceinline__ void bicubic_w(int i, float w[4]) {
    float s = (i + 0.5f) * 0.25f - 0.5f;
    float tot = 0.f;
#pragma unroll
    for (int j = 0; j < 4; j++) {
        float x = fabsf(s - (float)j);
        float v;
        if (x >= 2.f)      v = 0.f;
        else if (x >= 1.f) v = ((-0.5f * x + 2.5f) * x - 4.f) * x + 2.f;
        else               v = ((1.5f * x - 2.5f) * x) * x + 1.f;
        w[j] = v; tot += v;
    }
    float inv = 1.f / tot;
#pragma unroll
    for (int j = 0; j < 4; j++) w[j] *= inv;
}

// ---------------- patchify + pos-embed ----------------
__global__ void __launch_bounds__(288) patchify_kernel(
    const float* __restrict__ x, const float* __restrict__ pw,
    const float* __restrict__ pb, const float* __restrict__ pe)
{
    int t = blockIdx.x;
    int b = t >> 8, gy = (t >> 4) & 15, gx = t & 15;

    float xr[16];
#pragma unroll
    for (int ic = 0; ic < 4; ic++)
#pragma unroll
        for (int py = 0; py < 2; py++)
#pragma unroll
            for (int px = 0; px < 2; px++)
                xr[ic * 4 + py * 2 + px] =
                    x[(((size_t)b * 4 + ic) * 32 + (gy * 2 + py)) * 32 + gx * 2 + px];

    float wy[4], wx[4];
    bicubic_w(gy, wy); bicubic_w(gx, wx);
    float wyx[16];
#pragma unroll
    for (int jy = 0; jy < 4; jy++)
#pragma unroll
        for (int jx = 0; jx < 4; jx++) wyx[jy * 4 + jx] = wy[jy] * wx[jx];

    for (int o = threadIdx.x; o < HID; o += 288) {
        float a = pb[o];
        const float* w = pw + (size_t)o * 16;
#pragma unroll
        for (int qq = 0; qq < 16; qq++) a += xr[qq] * w[qq];
        float p = 0.f;
#pragma unroll
        for (int qq = 0; qq < 16; qq++) p += wyx[qq] * pe[(size_t)qq * HID + o];
        g_h[(size_t)t * HID + o] = a + p;
    }
}

// ---------------- LN + adaLN modulate (tf32-rounded output) ----------------
__global__ void __launch_bounds__(288) ln_mod_kernel(
    const float* __restrict__ sh, const float* __restrict__ sc, int mstride)
{
    int t = blockIdx.x;
    int b = t >> 8;
    int tid = threadIdx.x;
    const float* row = g_h + (size_t)t * HID;
    float v[4]; float s = 0.f, s2 = 0.f;
#pragma unroll
    for (int k = 0; k < 4; k++) {
        float xv = row[tid + k * 288];
        v[k] = xv; s += xv; s2 += xv * xv;
    }
#pragma unroll
    for (int o = 16; o > 0; o >>= 1) {
        s  += __shfl_xor_sync(0xffffffffu, s, o);
        s2 += __shfl_xor_sync(0xffffffffu, s2, o);
    }
    __shared__ float ws[9], ws2[9];
    int w = tid >> 5, lane = tid & 31;
    if (lane == 0) { ws[w] = s; ws2[w] = s2; }
    __syncthreads();
    if (tid == 0) {
        float a = 0.f, a2 = 0.f;
        for (int i = 0; i < 9; i++) { a += ws[i]; a2 += ws2[i]; }
        ws[0] = a; ws2[0] = a2;
    }
    __syncthreads();
    float mean = ws[0] * (1.f / HID);
    float var  = ws2[0] * (1.f / HID) - mean * mean;
    float rstd = rsqrtf(var + 1e-6f);
    const float* shr = sh + (size_t)b * mstride;
    const float* scr = sc + (size_t)b * mstride;
    float* orow = g_x1 + (size_t)t * HID;
#pragma unroll
    for (int k = 0; k < 4; k++) {
        int j = tid + k * 288;
        float xm = (v[k] - mean) * rstd;
        orow[j] = tf32r(xm * (1.f + scr[j]) + shr[j]);
    }
}

// ---------------- neighborhood attention (tf32-rounded output) ----------------
__global__ void __launch_bounds__(256) attn_kernel()
{
    int t = blockIdx.x;
    int b = t >> 8, i = (t >> 4) & 15, j = t & 15;
    int tid = threadIdx.x;
    int h = tid >> 4, p = tid & 15;

    __shared__ int   ntok[16];
    __shared__ float att[16][16];

    if (tid < 16) {
        int py = tid >> 2, px = tid & 3;
        int si = min(max(i - 2, 0), 12);
        int sj = min(max(j - 2, 0), 12);
        ntok[tid] = (b << 8) | ((si + py) << 4) | (sj + px);
    }
    __syncthreads();

    const float* qrow = g_qkv + (size_t)t * QKVN + h * DH;
    const float* krow = g_qkv + (size_t)ntok[p] * QKVN + HID + h * DH;
    float acc = 0.f;
#pragma unroll 8
    for (int d = 0; d < DH; d++) acc += qrow[d] * krow[d];
    acc *= 0.11785113019775793f;

    float m = acc;
#pragma unroll
    for (int o = 8; o > 0; o >>= 1) m = fmaxf(m, __shfl_xor_sync(0xffffffffu, m, o, 16));
    float e = expf(acc - m);
    float s = e;
#pragma unroll
    for (int o = 8; o > 0; o >>= 1) s += __shfl_xor_sync(0xffffffffu, s, o, 16);
    att[h][p] = e / s;
    __syncthreads();

    for (int o = tid; o < HID; o += 256) {
        int hh = o / DH;
        float sum = 0.f;
#pragma unroll
        for (int p2 = 0; p2 < 16; p2++)
            sum += att[hh][p2] * g_qkv[(size_t)ntok[p2] * QKVN + 2304 + o];
        g_ao[(size_t)t * HID + o] = tf32r(sum);
    }
}

// ---------------- final linear + unpatchify ----------------
__global__ void __launch_bounds__(256) final_kernel(
    const float* __restrict__ flw, const float* __restrict__ flb, float* __restrict__ out)
{
    int t = blockIdx.x;
    int b = t >> 8, gy = (t >> 4) & 15, gx = t & 15;
    __shared__ float xs[HID];
    __shared__ float part[8][32];
    int tid = threadIdx.x;
    for (int k = tid; k < HID; k += 256) xs[k] = g_x1[(size_t)t * HID + k];
    __syncthreads();
    int col = tid & 31, seg = tid >> 5;
    float acc = 0.f;
    int k0 = seg * 144;
    for (int k = k0; k < k0 + 144; k++)
        acc += xs[k] * flw[(size_t)k * 32 + col];
    part[seg][col] = acc;
    __syncthreads();
    if (tid < 32) {
        float s = flb[tid];
#pragma unroll
        for (int sg = 0; sg < 8; sg++) s += part[sg][tid];
        int ch = tid & 7, pq = tid >> 3, p = pq >> 1, q = pq & 1;
        out[(((size_t)b * 8 + ch) * 32 + gy * 2 + p) * 32 + gx * 2 + q] = s;
    }
}

// ---------------- launch ----------------
extern "C" void kernel_launch(void* const* d_in, const int* in_sizes, int n_in,
                              void* d_out, int out_size)
{
    const float* x    = (const float*)d_in[0];
    const float* tin  = (const float*)d_in[1];
    const int*   y    = (const int*)  d_in[2];
    const float* pos  = (const float*)d_in[3];
    const float* pw   = (const float*)d_in[4];
    const float* pb   = (const float*)d_in[5];
    const float* tw1  = (const float*)d_in[6];
    const float* tb1  = (const float*)d_in[7];
    const float* tw2  = (const float*)d_in[8];
    const float* tb2  = (const float*)d_in[9];
    const float* ytab = (const float*)d_in[10];
    const float* adaw = (const float*)d_in[11];
    const float* adab = (const float*)d_in[12];
    const float* qkvw = (const float*)d_in[13];
    const float* qkvb = (const float*)d_in[14];
    const float* prjw = (const float*)d_in[15];
    const float* prjb = (const float*)d_in[16];
    const float* m1w  = (const float*)d_in[17];
    const float* m1b  = (const float*)d_in[18];
    const float* m2w  = (const float*)d_in[19];
    const float* m2b  = (const float*)d_in[20];
    const float* flaw = (const float*)d_in[21];
    const float* flab = (const float*)d_in[22];
    const float* flw  = (const float*)d_in[23];
    const float* flb  = (const float*)d_in[24];
    float* out = (float*)d_out;

    float *p_x1, *p_qkv, *p_ao, *p_mh, *p_h, *p_mod, *p_fmod, *p_te, *p_e1, *p_scb;
    cudaGetSymbolAddress((void**)&p_x1,  g_x1);
    cudaGetSymbolAddress((void**)&p_qkv, g_qkv);
    cudaGetSymbolAddress((void**)&p_ao,  g_ao);
    cudaGetSymbolAddress((void**)&p_mh,  g_mh);
    cudaGetSymbolAddress((void**)&p_h,   g_h);
    cudaGetSymbolAddress((void**)&p_mod, g_mod);
    cudaGetSymbolAddress((void**)&p_fmod, g_fmod);
    cudaGetSymbolAddress((void**)&p_te,  g_te);
    cudaGetSymbolAddress((void**)&p_e1,  g_e1);
    cudaGetSymbolAddress((void**)&p_scb, g_scb);

    cudaFuncSetAttribute(mma_gemm<0>, cudaFuncAttributeMaxDynamicSharedMemorySize, GSME);
    cudaFuncSetAttribute(mma_gemm<1>, cudaFuncAttributeMaxDynamicSharedMemorySize, GSME);
    cudaFuncSetAttribute(mma_gemm<2>, cudaFuncAttributeMaxDynamicSharedMemorySize, GSME);

    patchify_kernel<<<TOK, 288>>>(x, pw, pb, pos);

    // conditioning path: te -> e1 -> scb
    te_kernel<<<BATCH, 256>>>(tin);
    smk_part<<<dim3(HID / 128, 2), 128>>>(p_te, tw1, HID);
    smk_reduce<1><<<HID / 128, 128>>>(tb1, nullptr, nullptr, p_e1, HID, 2);
    smk_part<<<dim3(HID / 128, 9), 128>>>(p_e1, tw2, HID);
    smk_reduce<2><<<HID / 128, 128>>>(tb2, ytab, y, p_scb, HID, 9);

    for (int l = 0; l < 2; l++) {
        const float* aw = adaw + (size_t)l * HID * ADAN;
        const float* ab = adab + (size_t)l * ADAN;
        smk_part<<<dim3(ADAN / 128, 9), 128>>>(p_scb, aw, ADAN);
        smk_reduce<0><<<ADAN / 128, 128>>>(ab, nullptr, nullptr, p_mod, ADAN, 9);

        // attention block
        ln_mod_kernel<<<TOK, 288>>>(p_mod + 0, p_mod + HID, ADAN);
        mma_gemm<0><<<dim3(QKVN / 128, TOK / 128), 256, GSME>>>(
            p_x1, qkvw + (size_t)l * HID * QKVN, qkvb + (size_t)l * QKVN,
            p_qkv, nullptr, 0, QKVN, HID);
        attn_kernel<<<TOK, 256>>>();
        mma_gemm<2><<<dim3(HID / 128, TOK / 128), 256, GSME>>>(
            p_ao, prjw + (size_t)l * HID * HID, prjb + (size_t)l * HID,
            p_h, p_mod + 2 * HID, ADAN, HID, HID);

        // mlp block
        ln_mod_kernel<<<TOK, 288>>>(p_mod + 3 * HID, p_mod + 4 * HID, ADAN);
        mma_gemm<1><<<dim3(MLPN / 128, TOK / 128), 256, GSME>>>(
            p_x1, m1w + (size_t)l * HID * MLPN, m1b + (size_t)l * MLPN,
            p_mh, nullptr, 0, MLPN, HID);
        mma_gemm<2><<<dim3(HID / 128, TOK / 128), 256, GSME>>>(
            p_mh, m2w + (size_t)l * MLPN * HID, m2b + (size_t)l * HID,
            p_h, p_mod + 5 * HID, ADAN, HID, MLPN);
    }

    smk_part<<<dim3(2304 / 128, 9), 128>>>(p_scb, flaw, 2304);
    smk_reduce<0><<<2304 / 128, 128>>>(flab, nullptr, nullptr, p_fmod, 2304, 9);
    ln_mod_kernel<<<TOK, 288>>>(p_fmod + 0, p_fmod + HID, 2304);
    final_kernel<<<TOK, 256>>>(flw, flb, out);

    (void)in_sizes; (void)n_in; (void)out_size;
}

// round 6
// speedup vs baseline: 2.0917x; 1.3760x over previous
#include <cuda_runtime.h>
#include <cuda_fp16.h>
#include <cstdint>
#include <cstddef>

// ---------------- constants ----------------
#define BATCH   16
#define TOK     4096
#define HID     1152
#define QKVN    3456
#define MLPN    4608
#define ADAN    6912
#define DH      72

#define OFF_QKV  0
#define OFF_PROJ 3981312
#define OFF_M1   5308416
#define OFF_M2   10616832
#define LSZ      15925248

// ---------------- scratch ----------------
__device__ float  g_h   [TOK * HID];
__device__ float  g_qkv [TOK * QKVN];
__device__ __half g_x1h [TOK * HID];
__device__ __half g_aoh [TOK * HID];
__device__ __half g_mhh [TOK * MLPN];
__device__ __half g_wh  [2 * LSZ];
__device__ float  g_te  [BATCH * 256];
__device__ float  g_e1  [BATCH * HID];
__device__ float  g_scb [BATCH * HID];
__device__ float  g_mod [BATCH * ADAN];
__device__ float  g_fmod[BATCH * 2304];
__device__ float  g_part[9 * BATCH * ADAN];

// ---------------- helpers ----------------
__device__ __forceinline__ float silu_f(float x) { return x / (1.f + expf(-x)); }
__device__ __forceinline__ float gelu_f(float x) {
    float x3 = x * x * x;
    return 0.5f * x * (1.f + tanhf(0.7978845608028654f * (x + 0.044715f * x3)));
}
__device__ __forceinline__ uint32_t su32(const void* p) {
    uint32_t a;
    asm("{ .reg .u64 t; cvta.to.shared.u64 t, %1; cvt.u32.u64 %0, t; }" : "=r"(a) : "l"(p));
    return a;
}
__device__ __forceinline__ void cpa16(uint32_t dst, const void* src) {
    asm volatile("cp.async.cg.shared.global [%0], [%1], 16;" :: "r"(dst), "l"(src) : "memory");
}
__device__ __forceinline__ void cpa_commit() {
    asm volatile("cp.async.commit_group;" ::: "memory");
}
__device__ __forceinline__ void ldsm4(uint32_t* r, uint32_t a) {
    asm volatile("ldmatrix.sync.aligned.m8n8.x4.shared.b16 {%0,%1,%2,%3}, [%4];"
                 : "=r"(r[0]), "=r"(r[1]), "=r"(r[2]), "=r"(r[3]) : "r"(a));
}
__device__ __forceinline__ void ldsm4t(uint32_t* r, uint32_t a) {
    asm volatile("ldmatrix.sync.aligned.m8n8.x4.trans.shared.b16 {%0,%1,%2,%3}, [%4];"
                 : "=r"(r[0]), "=r"(r[1]), "=r"(r[2]), "=r"(r[3]) : "r"(a));
}
__device__ __forceinline__ void mma16816(float* d, const uint32_t* a, const uint32_t* b) {
    asm volatile("mma.sync.aligned.m16n8k16.row.col.f32.f16.f16.f32 "
                 "{%0,%1,%2,%3}, {%4,%5,%6,%7}, {%8,%9}, {%0,%1,%2,%3};"
                 : "+f"(d[0]), "+f"(d[1]), "+f"(d[2]), "+f"(d[3])
                 : "r"(a[0]), "r"(a[1]), "r"(a[2]), "r"(a[3]), "r"(b[0]), "r"(b[1]));
}

// ---------------- weight fp32 -> fp16 mirror ----------------
__global__ void __launch_bounds__(256) w2h_kernel(
    const float* __restrict__ src, __half* __restrict__ dst, int n)
{
    int i = (blockIdx.x * 256 + threadIdx.x) * 4;
    if (i < n) {
        float4 v = *(const float4*)(src + i);
        __half2* d = (__half2*)(dst + i);
        d[0] = __floats2half2_rn(v.x, v.y);
        d[1] = __floats2half2_rn(v.z, v.w);
    }
}

// ---------------- fp16 mma.sync GEMM: C[4096 x N] = A[4096 x K] * Wh[K x N] ----------------
// EPI 0: (float)C = acc + bias
// EPI 1: (half) C = gelu(acc + bias)
// EPI 2: (float)C += gate[b][n] * (acc + bias)
// smem: As 2 x [128][40] halves, Bs 2 x [32][136] halves (both conflict-free for LDSM)
#define GSME 37888

template<int EPI>
__global__ void __launch_bounds__(256, 2) mma_gemm(
    const __half* __restrict__ A, const __half* __restrict__ Wh,
    const float* __restrict__ bias, void* __restrict__ Cv,
    const float* __restrict__ gate, int gstride, int N, int K)
{
    extern __shared__ char smc[];
    uint32_t smB = su32(smc);            // As at 0 (buf stride 10240 B), Bs at 20480 (buf stride 8704 B)

    int tid = threadIdx.x;
    int m0 = blockIdx.y * 128, n0 = blockIdx.x * 128;
    int lane = tid & 31, wid = tid >> 5;
    int wm = wid >> 2, wn = wid & 3;     // warp tile 64 x 32
    int g = lane >> 2, q = lane & 3;
    int l15 = lane & 15, lhi = lane >> 4;

    const __half* Abase = A + (size_t)m0 * K;
    const __half* Wbase = Wh + n0;

    const int NC = K >> 5;
    float acc[4][4][4];
#pragma unroll
    for (int i = 0; i < 4; i++)
#pragma unroll
        for (int j = 0; j < 4; j++)
#pragma unroll
            for (int r = 0; r < 4; r++) acc[i][j][r] = 0.f;

    // prefetch chunk 0 -> buf 0
#pragma unroll
    for (int i = 0; i < 2; i++) {
        int idx = tid + i * 256;
        int ar = idx >> 2, ac8 = (idx & 3) * 8;
        cpa16(smB + (uint32_t)(ar * 80 + ac8 * 2), Abase + (size_t)ar * K + ac8);
        int bk = idx >> 4, bn8 = (idx & 15) * 8;
        cpa16(smB + 20480u + (uint32_t)(bk * 272 + bn8 * 2), Wbase + (size_t)bk * N + bn8);
    }
    cpa_commit();

    for (int c = 0; c < NC; c++) {
        int buf = c & 1;
        if (c + 1 < NC) {
            int nb = buf ^ 1;
            const __half* Ab = Abase + (c + 1) * 32;
            const __half* Wb = Wbase + (size_t)((c + 1) * 32) * N;
#pragma unroll
            for (int i = 0; i < 2; i++) {
                int idx = tid + i * 256;
                int ar = idx >> 2, ac8 = (idx & 3) * 8;
                cpa16(smB + (uint32_t)(nb * 10240 + ar * 80 + ac8 * 2), Ab + (size_t)ar * K + ac8);
                int bk = idx >> 4, bn8 = (idx & 15) * 8;
                cpa16(smB + 20480u + (uint32_t)(nb * 8704 + bk * 272 + bn8 * 2), Wb + (size_t)bk * N + bn8);
            }
            cpa_commit();
            asm volatile("cp.async.wait_group 1;" ::: "memory");
        } else {
            asm volatile("cp.async.wait_group 0;" ::: "memory");
        }
        __syncthreads();

        uint32_t aB = smB + buf * 10240u;
        uint32_t bB = smB + 20480u + buf * 8704u;
#pragma unroll
        for (int ks = 0; ks < 2; ks++) {
            uint32_t af[4][4], bf[2][4];
#pragma unroll
            for (int mi = 0; mi < 4; mi++)
                ldsm4(af[mi], aB + (uint32_t)(((wm * 64 + mi * 16 + l15) * 40 + ks * 16 + lhi * 8) * 2));
#pragma unroll
            for (int nh = 0; nh < 2; nh++)
                ldsm4t(bf[nh], bB + (uint32_t)(((ks * 16 + l15) * 136 + wn * 32 + nh * 16 + lhi * 8) * 2));
#pragma unroll
            for (int mi = 0; mi < 4; mi++)
#pragma unroll
                for (int ni = 0; ni < 4; ni++)
                    mma16816(acc[mi][ni], af[mi], &bf[ni >> 1][(ni & 1) * 2]);
        }
        __syncthreads();
    }

    // ---- epilogue ----
    int bidx = m0 >> 8;
#pragma unroll
    for (int mi = 0; mi < 4; mi++) {
#pragma unroll
        for (int half = 0; half < 2; half++) {
            int row = m0 + wm * 64 + mi * 16 + g + half * 8;
#pragma unroll
            for (int ni = 0; ni < 4; ni++) {
                int col = n0 + wn * 32 + ni * 8 + 2 * q;
                float2 bv = *(const float2*)(bias + col);
                float v0 = acc[mi][ni][half * 2 + 0] + bv.x;
                float v1 = acc[mi][ni][half * 2 + 1] + bv.y;
                if (EPI == 1) {
                    __half* Crow = (__half*)Cv + (size_t)row * N;
                    *(__half2*)(Crow + col) = __floats2half2_rn(gelu_f(v0), gelu_f(v1));
                } else if (EPI == 2) {
                    float* Crow = (float*)Cv + (size_t)row * N;
                    float2 gv = *(const float2*)(gate + (size_t)bidx * gstride + col);
                    float2 cv = *(float2*)(Crow + col);
                    cv.x += gv.x * v0; cv.y += gv.y * v1;
                    *(float2*)(Crow + col) = cv;
                } else {
                    float* Crow = (float*)Cv + (size_t)row * N;
                    *(float2*)(Crow + col) = make_float2(v0, v1);
                }
            }
        }
    }
}

// ---------------- conditioning path: split-K small-M GEMM ----------------
__global__ void __launch_bounds__(128) smk_part(
    const float* __restrict__ Abuf, const float* __restrict__ W, int N)
{
    __shared__ float s[BATCH * 128];
    int tid = threadIdx.x;
    int kz = blockIdx.y;
    int j = blockIdx.x * 128 + tid;
    for (int i = tid; i < BATCH * 128; i += 128) {
        int b = i >> 7, kk = i & 127;
        s[b * 128 + kk] = Abuf[b * ((int)gridDim.y * 128) + kz * 128 + kk];
    }
    __syncthreads();
    float acc[BATCH];
#pragma unroll
    for (int b = 0; b < BATCH; b++) acc[b] = 0.f;
    const float* Wp = W + (size_t)(kz * 128) * N + j;
#pragma unroll 4
    for (int kk = 0; kk < 128; kk++) {
        float wv = Wp[(size_t)kk * N];
#pragma unroll
        for (int b = 0; b < BATCH; b++) acc[b] = fmaf(s[b * 128 + kk], wv, acc[b]);
    }
#pragma unroll
    for (int b = 0; b < BATCH; b++)
        g_part[(size_t)(kz * BATCH + b) * N + j] = acc[b];
}

// EPI 0: out = sum + bias ; 1: silu(sum+bias) ; 2: silu(sum+bias+ytab[y[b]])
template<int EPI>
__global__ void __launch_bounds__(128) smk_reduce(
    const float* __restrict__ bias, const float* __restrict__ ytab,
    const int* __restrict__ y, float* __restrict__ out, int N, int KS)
{
    int j = blockIdx.x * 128 + threadIdx.x;
    int b = blockIdx.y;
    float acc = bias[j];
    for (int kz = 0; kz < KS; kz++)
        acc += g_part[(size_t)(kz * BATCH + b) * N + j];
    if (EPI == 1) acc = silu_f(acc);
    if (EPI == 2) acc = silu_f(acc + ytab[(size_t)y[b] * HID + j]);
    out[(size_t)b * N + j] = acc;
}

__global__ void __launch_bounds__(256) te_kernel(const float* __restrict__ tin)
{
    int b = blockIdx.x, k = threadIdx.x;
    float fr = expf(-9.210340371976184f * (float)(k & 127) / 128.f);
    float arg = tin[b] * fr;
    g_te[b * 256 + k] = (k < 128) ? cosf(arg) : sinf(arg);
}

// ---------------- bicubic ----------------
__device__ __forceinline__ void bicubic_w(int i, float w[4]) {
    float s = (i + 0.5f) * 0.25f - 0.5f;
    float tot = 0.f;
#pragma unroll
    for (int j = 0; j < 4; j++) {
        float x = fabsf(s - (float)j);
        float v;
        if (x >= 2.f)      v = 0.f;
        else if (x >= 1.f) v = ((-0.5f * x + 2.5f) * x - 4.f) * x + 2.f;
        else               v = ((1.5f * x - 2.5f) * x) * x + 1.f;
        w[j] = v; tot += v;
    }
    float inv = 1.f / tot;
#pragma unroll
    for (int j = 0; j < 4; j++) w[j] *= inv;
}

// ---------------- patchify + pos-embed ----------------
__global__ void __launch_bounds__(288) patchify_kernel(
    const float* __restrict__ x, const float* __restrict__ pw,
    const float* __restrict__ pb, const float* __restrict__ pe)
{
    int t = blockIdx.x;
    int b = t >> 8, gy = (t >> 4) & 15, gx = t & 15;

    float xr[16];
#pragma unroll
    for (int ic = 0; ic < 4; ic++)
#pragma unroll
        for (int py = 0; py < 2; py++)
#pragma unroll
            for (int px = 0; px < 2; px++)
                xr[ic * 4 + py * 2 + px] =
                    x[(((size_t)b * 4 + ic) * 32 + (gy * 2 + py)) * 32 + gx * 2 + px];

    float wy[4], wx[4];
    bicubic_w(gy, wy); bicubic_w(gx, wx);
    float wyx[16];
#pragma unroll
    for (int jy = 0; jy < 4; jy++)
#pragma unroll
        for (int jx = 0; jx < 4; jx++) wyx[jy * 4 + jx] = wy[jy] * wx[jx];

    for (int o = threadIdx.x; o < HID; o += 288) {
        float a = pb[o];
        const float* w = pw + (size_t)o * 16;
#pragma unroll
        for (int qq = 0; qq < 16; qq++) a += xr[qq] * w[qq];
        float p = 0.f;
#pragma unroll
        for (int qq = 0; qq < 16; qq++) p += wyx[qq] * pe[(size_t)qq * HID + o];
        g_h[(size_t)t * HID + o] = a + p;
    }
}

// ---------------- LN + adaLN modulate (fp16 output) ----------------
__global__ void __launch_bounds__(288) ln_mod_kernel(
    const float* __restrict__ sh, const float* __restrict__ sc, int mstride)
{
    int t = blockIdx.x;
    int b = t >> 8;
    int tid = threadIdx.x;
    const float* row = g_h + (size_t)t * HID;
    float v[4]; float s = 0.f, s2 = 0.f;
#pragma unroll
    for (int k = 0; k < 4; k++) {
        float xv = row[tid + k * 288];
        v[k] = xv; s += xv; s2 += xv * xv;
    }
#pragma unroll
    for (int o = 16; o > 0; o >>= 1) {
        s  += __shfl_xor_sync(0xffffffffu, s, o);
        s2 += __shfl_xor_sync(0xffffffffu, s2, o);
    }
    __shared__ float ws[9], ws2[9];
    int w = tid >> 5, lane = tid & 31;
    if (lane == 0) { ws[w] = s; ws2[w] = s2; }
    __syncthreads();
    if (tid == 0) {
        float a = 0.f, a2 = 0.f;
        for (int i = 0; i < 9; i++) { a += ws[i]; a2 += ws2[i]; }
        ws[0] = a; ws2[0] = a2;
    }
    __syncthreads();
    float mean = ws[0] * (1.f / HID);
    float var  = ws2[0] * (1.f / HID) - mean * mean;
    float rstd = rsqrtf(var + 1e-6f);
    const float* shr = sh + (size_t)b * mstride;
    const float* scr = sc + (size_t)b * mstride;
    __half* orow = g_x1h + (size_t)t * HID;
#pragma unroll
    for (int k = 0; k < 4; k++) {
        int j = tid + k * 288;
        float xm = (v[k] - mean) * rstd;
        orow[j] = __float2half(xm * (1.f + scr[j]) + shr[j]);
    }
}

// ---------------- neighborhood attention (fp16 output) ----------------
__global__ void __launch_bounds__(256) attn_kernel()
{
    int t = blockIdx.x;
    int b = t >> 8, i = (t >> 4) & 15, j = t & 15;
    int tid = threadIdx.x;
    int h = tid >> 4, p = tid & 15;

    __shared__ int   ntok[16];
    __shared__ float att[16][16];

    if (tid < 16) {
        int py = tid >> 2, px = tid & 3;
        int si = min(max(i - 2, 0), 12);
        int sj = min(max(j - 2, 0), 12);
        ntok[tid] = (b << 8) | ((si + py) << 4) | (sj + px);
    }
    __syncthreads();

    const float* qrow = g_qkv + (size_t)t * QKVN + h * DH;
    const float* krow = g_qkv + (size_t)ntok[p] * QKVN + HID + h * DH;
    float acc = 0.f;
#pragma unroll 8
    for (int d = 0; d < DH; d++) acc += qrow[d] * krow[d];
    acc *= 0.11785113019775793f;

    float m = acc;
#pragma unroll
    for (int o = 8; o > 0; o >>= 1) m = fmaxf(m, __shfl_xor_sync(0xffffffffu, m, o, 16));
    float e = expf(acc - m);
    float s = e;
#pragma unroll
    for (int o = 8; o > 0; o >>= 1) s += __shfl_xor_sync(0xffffffffu, s, o, 16);
    att[h][p] = e / s;
    __syncthreads();

    for (int o = tid; o < HID; o += 256) {
        int hh = o / DH;
        float sum = 0.f;
#pragma unroll
        for (int p2 = 0; p2 < 16; p2++)
            sum += att[hh][p2] * g_qkv[(size_t)ntok[p2] * QKVN + 2304 + o];
        g_aoh[(size_t)t * HID + o] = __float2half(sum);
    }
}

// ---------------- final linear + unpatchify ----------------
__global__ void __launch_bounds__(256) final_kernel(
    const float* __restrict__ flw, const float* __restrict__ flb, float* __restrict__ out)
{
    int t = blockIdx.x;
    int b = t >> 8, gy = (t >> 4) & 15, gx = t & 15;
    __shared__ float xs[HID];
    __shared__ float part[8][32];
    int tid = threadIdx.x;
    for (int k = tid; k < HID; k += 256) xs[k] = __half2float(g_x1h[(size_t)t * HID + k]);
    __syncthreads();
    int col = tid & 31, seg = tid >> 5;
    float acc = 0.f;
    int k0 = seg * 144;
    for (int k = k0; k < k0 + 144; k++)
        acc += xs[k] * flw[(size_t)k * 32 + col];
    part[seg][col] = acc;
    __syncthreads();
    if (tid < 32) {
        float s = flb[tid];
#pragma unroll
        for (int sg = 0; sg < 8; sg++) s += part[sg][tid];
        int ch = tid & 7, pq = tid >> 3, p = pq >> 1, q = pq & 1;
        out[(((size_t)b * 8 + ch) * 32 + gy * 2 + p) * 32 + gx * 2 + q] = s;
    }
}

// ---------------- launch ----------------
extern "C" void kernel_launch(void* const* d_in, const int* in_sizes, int n_in,
                              void* d_out, int out_size)
{
    const float* x    = (const float*)d_in[0];
    const float* tin  = (const float*)d_in[1];
    const int*   y    = (const int*)  d_in[2];
    const float* pos  = (const float*)d_in[3];
    const float* pw   = (const float*)d_in[4];
    const float* pb   = (const float*)d_in[5];
    const float* tw1  = (const float*)d_in[6];
    const float* tb1  = (const float*)d_in[7];
    const float* tw2  = (const float*)d_in[8];
    const float* tb2  = (const float*)d_in[9];
    const float* ytab = (const float*)d_in[10];
    const float* adaw = (const float*)d_in[11];
    const float* adab = (const float*)d_in[12];
    const float* qkvw = (const float*)d_in[13];
    const float* qkvb = (const float*)d_in[14];
    const float* prjw = (const float*)d_in[15];
    const float* prjb = (const float*)d_in[16];
    const float* m1w  = (const float*)d_in[17];
    const float* m1b  = (const float*)d_in[18];
    const float* m2w  = (const float*)d_in[19];
    const float* m2b  = (const float*)d_in[20];
    const float* flaw = (const float*)d_in[21];
    const float* flab = (const float*)d_in[22];
    const float* flw  = (const float*)d_in[23];
    const float* flb  = (const float*)d_in[24];
    float* out = (float*)d_out;

    float *p_qkv, *p_h, *p_mod, *p_fmod, *p_te, *p_e1, *p_scb;
    __half *p_x1h, *p_aoh, *p_mhh, *p_wh;
    cudaGetSymbolAddress((void**)&p_qkv, g_qkv);
    cudaGetSymbolAddress((void**)&p_h,   g_h);
    cudaGetSymbolAddress((void**)&p_mod, g_mod);
    cudaGetSymbolAddress((void**)&p_fmod, g_fmod);
    cudaGetSymbolAddress((void**)&p_te,  g_te);
    cudaGetSymbolAddress((void**)&p_e1,  g_e1);
    cudaGetSymbolAddress((void**)&p_scb, g_scb);
    cudaGetSymbolAddress((void**)&p_x1h, g_x1h);
    cudaGetSymbolAddress((void**)&p_aoh, g_aoh);
    cudaGetSymbolAddress((void**)&p_mhh, g_mhh);
    cudaGetSymbolAddress((void**)&p_wh,  g_wh);

    cudaFuncSetAttribute(mma_gemm<0>, cudaFuncAttributeMaxDynamicSharedMemorySize, GSME);
    cudaFuncSetAttribute(mma_gemm<1>, cudaFuncAttributeMaxDynamicSharedMemorySize, GSME);
    cudaFuncSetAttribute(mma_gemm<2>, cudaFuncAttributeMaxDynamicSharedMemorySize, GSME);

    // weight fp16 mirrors
    for (int l = 0; l < 2; l++) {
        w2h_kernel<<<HID * QKVN / 1024, 256>>>(qkvw + (size_t)l * HID * QKVN, p_wh + (size_t)l * LSZ + OFF_QKV, HID * QKVN);
        w2h_kernel<<<HID * HID  / 1024, 256>>>(prjw + (size_t)l * HID * HID,  p_wh + (size_t)l * LSZ + OFF_PROJ, HID * HID);
        w2h_kernel<<<HID * MLPN / 1024, 256>>>(m1w  + (size_t)l * HID * MLPN, p_wh + (size_t)l * LSZ + OFF_M1, HID * MLPN);
        w2h_kernel<<<MLPN * HID / 1024, 256>>>(m2w  + (size_t)l * MLPN * HID, p_wh + (size_t)l * LSZ + OFF_M2, MLPN * HID);
    }

    patchify_kernel<<<TOK, 288>>>(x, pw, pb, pos);

    // conditioning path
    te_kernel<<<BATCH, 256>>>(tin);
    smk_part<<<dim3(HID / 128, 2), 128>>>(p_te, tw1, HID);
    smk_reduce<1><<<dim3(HID / 128, BATCH), 128>>>(tb1, nullptr, nullptr, p_e1, HID, 2);
    smk_part<<<dim3(HID / 128, 9), 128>>>(p_e1, tw2, HID);
    smk_reduce<2><<<dim3(HID / 128, BATCH), 128>>>(tb2, ytab, y, p_scb, HID, 9);

    for (int l = 0; l < 2; l++) {
        const __half* whL = p_wh + (size_t)l * LSZ;
        const float* ab = adab + (size_t)l * ADAN;
        smk_part<<<dim3(ADAN / 128, 9), 128>>>(p_scb, adaw + (size_t)l * HID * ADAN, ADAN);
        smk_reduce<0><<<dim3(ADAN / 128, BATCH), 128>>>(ab, nullptr, nullptr, p_mod, ADAN, 9);

        // attention block
        ln_mod_kernel<<<TOK, 288>>>(p_mod + 0, p_mod + HID, ADAN);
        mma_gemm<0><<<dim3(QKVN / 128, TOK / 128), 256, GSME>>>(
            p_x1h, whL + OFF_QKV, qkvb + (size_t)l * QKVN, p_qkv, nullptr, 0, QKVN, HID);
        attn_kernel<<<TOK, 256>>>();
        mma_gemm<2><<<dim3(HID / 128, TOK / 128), 256, GSME>>>(
            p_aoh, whL + OFF_PROJ, prjb + (size_t)l * HID, p_h, p_mod + 2 * HID, ADAN, HID, HID);

        // mlp block
        ln_mod_kernel<<<TOK, 288>>>(p_mod + 3 * HID, p_mod + 4 * HID, ADAN);
        mma_gemm<1><<<dim3(MLPN / 128, TOK / 128), 256, GSME>>>(
            p_x1h, whL + OFF_M1, m1b + (size_t)l * MLPN, p_mhh, nullptr, 0, MLPN, HID);
        mma_gemm<2><<<dim3(HID / 128, TOK / 128), 256, GSME>>>(
            p_mhh, whL + OFF_M2, m2b + (size_t)l * HID, p_h, p_mod + 5 * HID, ADAN, HID, MLPN);
    }

    smk_part<<<dim3(2304 / 128, 9), 128>>>(p_scb, flaw, 2304);
    smk_reduce<0><<<dim3(2304 / 128, BATCH), 128>>>(flab, nullptr, nullptr, p_fmod, 2304, 9);
    ln_mod_kernel<<<TOK, 288>>>(p_fmod + 0, p_fmod + HID, 2304);
    final_kernel<<<TOK, 256>>>(flw, flb, out);

    (void)in_sizes; (void)n_in; (void)out_size;
}

// round 7
// speedup vs baseline: 2.3402x; 1.1188x over previous
#include <cuda_runtime.h>
#include <cuda_fp16.h>
#include <cstdint>
#include <cstddef>

// ---------------- constants ----------------
#define BATCH   16
#define TOK     4096
#define HID     1152
#define QKVN    3456
#define MLPN    4608
#define ADAN    6912
#define DH      72

#define OFF_QKV  0
#define OFF_PROJ 3981312
#define OFF_M1   5308416
#define OFF_M2   10616832
#define LSZ      15925248

// ---------------- scratch ----------------
__device__ float  g_h   [TOK * HID];
__device__ __half g_qkvh[TOK * QKVN];
__device__ __half g_x1h [TOK * HID];
__device__ __half g_aoh [TOK * HID];
__device__ __half g_mhh [TOK * MLPN];
__device__ __half g_wh  [2 * LSZ];
__device__ float  g_te  [BATCH * 256];
__device__ float  g_e1  [BATCH * HID];
__device__ float  g_scb [BATCH * HID];
__device__ float  g_mod [BATCH * ADAN];
__device__ float  g_fmod[BATCH * 2304];
__device__ float  g_part[9 * BATCH * ADAN];

// ---------------- helpers ----------------
__device__ __forceinline__ float silu_f(float x) { return x / (1.f + expf(-x)); }
__device__ __forceinline__ float gelu_f(float x) {
    float x3 = x * x * x;
    return 0.5f * x * (1.f + tanhf(0.7978845608028654f * (x + 0.044715f * x3)));
}
__device__ __forceinline__ uint32_t su32(const void* p) {
    uint32_t a;
    asm("{ .reg .u64 t; cvta.to.shared.u64 t, %1; cvt.u32.u64 %0, t; }" : "=r"(a) : "l"(p));
    return a;
}
__device__ __forceinline__ void cpa16(uint32_t dst, const void* src) {
    asm volatile("cp.async.cg.shared.global [%0], [%1], 16;" :: "r"(dst), "l"(src) : "memory");
}
__device__ __forceinline__ void cpa_commit() {
    asm volatile("cp.async.commit_group;" ::: "memory");
}
__device__ __forceinline__ void ldsm4(uint32_t* r, uint32_t a) {
    asm volatile("ldmatrix.sync.aligned.m8n8.x4.shared.b16 {%0,%1,%2,%3}, [%4];"
                 : "=r"(r[0]), "=r"(r[1]), "=r"(r[2]), "=r"(r[3]) : "r"(a));
}
__device__ __forceinline__ void ldsm4t(uint32_t* r, uint32_t a) {
    asm volatile("ldmatrix.sync.aligned.m8n8.x4.trans.shared.b16 {%0,%1,%2,%3}, [%4];"
                 : "=r"(r[0]), "=r"(r[1]), "=r"(r[2]), "=r"(r[3]) : "r"(a));
}
__device__ __forceinline__ void mma16816(float* d, const uint32_t* a, const uint32_t* b) {
    asm volatile("mma.sync.aligned.m16n8k16.row.col.f32.f16.f16.f32 "
                 "{%0,%1,%2,%3}, {%4,%5,%6,%7}, {%8,%9}, {%0,%1,%2,%3};"
                 : "+f"(d[0]), "+f"(d[1]), "+f"(d[2]), "+f"(d[3])
                 : "r"(a[0]), "r"(a[1]), "r"(a[2]), "r"(a[3]), "r"(b[0]), "r"(b[1]));
}

// ---------------- weight fp32 -> fp16 mirror ----------------
__global__ void __launch_bounds__(256) w2h_kernel(
    const float* __restrict__ src, __half* __restrict__ dst, int n)
{
    int i = (blockIdx.x * 256 + threadIdx.x) * 4;
    if (i < n) {
        float4 v = *(const float4*)(src + i);
        __half2* d = (__half2*)(dst + i);
        d[0] = __floats2half2_rn(v.x, v.y);
        d[1] = __floats2half2_rn(v.z, v.w);
    }
}

// ---------------- fp16 mma.sync GEMM, 3-stage cp.async pipeline ----------------
// EPI 0: (half) C = acc + bias
// EPI 1: (half) C = gelu(acc + bias)
// EPI 2: (float)C += gate[b][n] * (acc + bias)
// smem: As 3 x [128][40] halves (10240 B each), Bs 3 x [32][136] halves (8704 B each)
#define ABUF 10240u
#define BBUF 8704u
#define BS0  30720u
#define GSME 56832

template<int EPI>
__global__ void __launch_bounds__(256, 2) mma_gemm(
    const __half* __restrict__ A, const __half* __restrict__ Wh,
    const float* __restrict__ bias, void* __restrict__ Cv,
    const float* __restrict__ gate, int gstride, int N, int K)
{
    extern __shared__ char smc[];
    uint32_t smB = su32(smc);

    int tid = threadIdx.x;
    int m0 = blockIdx.y * 128, n0 = blockIdx.x * 128;
    int lane = tid & 31, wid = tid >> 5;
    int wm = wid >> 2, wn = wid & 3;     // warp tile 64 x 32
    int g = lane >> 2, q = lane & 3;
    int l15 = lane & 15, lhi = lane >> 4;

    const __half* Abase = A + (size_t)m0 * K;
    const __half* Wbase = Wh + n0;

    const int NC = K >> 5;
    float acc[4][4][4];
#pragma unroll
    for (int i = 0; i < 4; i++)
#pragma unroll
        for (int j = 0; j < 4; j++)
#pragma unroll
            for (int r = 0; r < 4; r++) acc[i][j][r] = 0.f;

    // prologue: load chunks 0 and 1 into bufs 0, 1
#pragma unroll
    for (int pc = 0; pc < 2; pc++) {
        const __half* Ab = Abase + pc * 32;
        const __half* Wb = Wbase + (size_t)(pc * 32) * N;
#pragma unroll
        for (int i = 0; i < 2; i++) {
            int idx = tid + i * 256;
            int ar = idx >> 2, ac8 = (idx & 3) * 8;
            cpa16(smB + pc * ABUF + (uint32_t)(ar * 80 + ac8 * 2), Ab + (size_t)ar * K + ac8);
            int bk = idx >> 4, bn8 = (idx & 15) * 8;
            cpa16(smB + BS0 + pc * BBUF + (uint32_t)(bk * 272 + bn8 * 2), Wb + (size_t)bk * N + bn8);
        }
        cpa_commit();
    }

    for (int c = 0; c < NC; c++) {
        int buf = c % 3;
        if (c + 1 < NC) asm volatile("cp.async.wait_group 1;" ::: "memory");
        else            asm volatile("cp.async.wait_group 0;" ::: "memory");
        __syncthreads();

        if (c + 2 < NC) {
            int nb = (c + 2) % 3;
            const __half* Ab = Abase + (c + 2) * 32;
            const __half* Wb = Wbase + (size_t)((c + 2) * 32) * N;
#pragma unroll
            for (int i = 0; i < 2; i++) {
                int idx = tid + i * 256;
                int ar = idx >> 2, ac8 = (idx & 3) * 8;
                cpa16(smB + nb * ABUF + (uint32_t)(ar * 80 + ac8 * 2), Ab + (size_t)ar * K + ac8);
                int bk = idx >> 4, bn8 = (idx & 15) * 8;
                cpa16(smB + BS0 + nb * BBUF + (uint32_t)(bk * 272 + bn8 * 2), Wb + (size_t)bk * N + bn8);
            }
            cpa_commit();
        }

        uint32_t aB = smB + buf * ABUF;
        uint32_t bB = smB + BS0 + buf * BBUF;
#pragma unroll
        for (int ks = 0; ks < 2; ks++) {
            uint32_t af[4][4], bf[2][4];
#pragma unroll
            for (int mi = 0; mi < 4; mi++)
                ldsm4(af[mi], aB + (uint32_t)(((wm * 64 + mi * 16 + l15) * 40 + ks * 16 + lhi * 8) * 2));
#pragma unroll
            for (int nh = 0; nh < 2; nh++)
                ldsm4t(bf[nh], bB + (uint32_t)(((ks * 16 + l15) * 136 + wn * 32 + nh * 16 + lhi * 8) * 2));
#pragma unroll
            for (int mi = 0; mi < 4; mi++)
#pragma unroll
                for (int ni = 0; ni < 4; ni++)
                    mma16816(acc[mi][ni], af[mi], &bf[ni >> 1][(ni & 1) * 2]);
        }
        __syncthreads();
    }

    // ---- epilogue ----
    int bidx = m0 >> 8;
#pragma unroll
    for (int mi = 0; mi < 4; mi++) {
#pragma unroll
        for (int half = 0; half < 2; half++) {
            int row = m0 + wm * 64 + mi * 16 + g + half * 8;
#pragma unroll
            for (int ni = 0; ni < 4; ni++) {
                int col = n0 + wn * 32 + ni * 8 + 2 * q;
                float2 bv = *(const float2*)(bias + col);
                float v0 = acc[mi][ni][half * 2 + 0] + bv.x;
                float v1 = acc[mi][ni][half * 2 + 1] + bv.y;
                if (EPI == 0) {
                    __half* Crow = (__half*)Cv + (size_t)row * N;
                    *(__half2*)(Crow + col) = __floats2half2_rn(v0, v1);
                } else if (EPI == 1) {
                    __half* Crow = (__half*)Cv + (size_t)row * N;
                    *(__half2*)(Crow + col) = __floats2half2_rn(gelu_f(v0), gelu_f(v1));
                } else {
                    float* Crow = (float*)Cv + (size_t)row * N;
                    float2 gv = *(const float2*)(gate + (size_t)bidx * gstride + col);
                    float2 cv = *(float2*)(Crow + col);
                    cv.x += gv.x * v0; cv.y += gv.y * v1;
                    *(float2*)(Crow + col) = cv;
                }
            }
        }
    }
}

// ---------------- conditioning path: split-K small-M GEMM ----------------
__global__ void __launch_bounds__(128) smk_part(
    const float* __restrict__ Abuf, const float* __restrict__ W, int N)
{
    __shared__ float s[BATCH * 128];
    int tid = threadIdx.x;
    int kz = blockIdx.y;
    int j = blockIdx.x * 128 + tid;
    for (int i = tid; i < BATCH * 128; i += 128) {
        int b = i >> 7, kk = i & 127;
        s[b * 128 + kk] = Abuf[b * ((int)gridDim.y * 128) + kz * 128 + kk];
    }
    __syncthreads();
    float acc[BATCH];
#pragma unroll
    for (int b = 0; b < BATCH; b++) acc[b] = 0.f;
    const float* Wp = W + (size_t)(kz * 128) * N + j;
#pragma unroll 4
    for (int kk = 0; kk < 128; kk++) {
        float wv = Wp[(size_t)kk * N];
#pragma unroll
        for (int b = 0; b < BATCH; b++) acc[b] = fmaf(s[b * 128 + kk], wv, acc[b]);
    }
#pragma unroll
    for (int b = 0; b < BATCH; b++)
        g_part[(size_t)(kz * BATCH + b) * N + j] = acc[b];
}

// EPI 0: out = sum + bias ; 1: silu(sum+bias) ; 2: silu(sum+bias+ytab[y[b]])
template<int EPI>
__global__ void __launch_bounds__(128) smk_reduce(
    const float* __restrict__ bias, const float* __restrict__ ytab,
    const int* __restrict__ y, float* __restrict__ out, int N, int KS)
{
    int j = blockIdx.x * 128 + threadIdx.x;
    int b = blockIdx.y;
    float acc = bias[j];
    for (int kz = 0; kz < KS; kz++)
        acc += g_part[(size_t)(kz * BATCH + b) * N + j];
    if (EPI == 1) acc = silu_f(acc);
    if (EPI == 2) acc = silu_f(acc + ytab[(size_t)y[b] * HID + j]);
    out[(size_t)b * N + j] = acc;
}

__global__ void __launch_bounds__(256) te_kernel(const float* __restrict__ tin)
{
    int b = blockIdx.x, k = threadIdx.x;
    float fr = expf(-9.210340371976184f * (float)(k & 127) / 128.f);
    float arg = tin[b] * fr;
    g_te[b * 256 + k] = (k < 128) ? cosf(arg) : sinf(arg);
}

// ---------------- bicubic ----------------
__device__ __forceinline__ void bicubic_w(int i, float w[4]) {
    float s = (i + 0.5f) * 0.25f - 0.5f;
    float tot = 0.f;
#pragma unroll
    for (int j = 0; j < 4; j++) {
        float x = fabsf(s - (float)j);
        float v;
        if (x >= 2.f)      v = 0.f;
        else if (x >= 1.f) v = ((-0.5f * x + 2.5f) * x - 4.f) * x + 2.f;
        else               v = ((1.5f * x - 2.5f) * x) * x + 1.f;
        w[j] = v; tot += v;
    }
    float inv = 1.f / tot;
#pragma unroll
    for (int j = 0; j < 4; j++) w[j] *= inv;
}

// ---------------- patchify + pos-embed ----------------
__global__ void __launch_bounds__(288) patchify_kernel(
    const float* __restrict__ x, const float* __restrict__ pw,
    const float* __restrict__ pb, const float* __restrict__ pe)
{
    int t = blockIdx.x;
    int b = t >> 8, gy = (t >> 4) & 15, gx = t & 15;

    float xr[16];
#pragma unroll
    for (int ic = 0; ic < 4; ic++)
#pragma unroll
        for (int py = 0; py < 2; py++)
#pragma unroll
            for (int px = 0; px < 2; px++)
                xr[ic * 4 + py * 2 + px] =
                    x[(((size_t)b * 4 + ic) * 32 + (gy * 2 + py)) * 32 + gx * 2 + px];

    float wy[4], wx[4];
    bicubic_w(gy, wy); bicubic_w(gx, wx);
    float wyx[16];
#pragma unroll
    for (int jy = 0; jy < 4; jy++)
#pragma unroll
        for (int jx = 0; jx < 4; jx++) wyx[jy * 4 + jx] = wy[jy] * wx[jx];

    for (int o = threadIdx.x; o < HID; o += 288) {
        float a = pb[o];
        const float* w = pw + (size_t)o * 16;
#pragma unroll
        for (int qq = 0; qq < 16; qq++) a += xr[qq] * w[qq];
        float p = 0.f;
#pragma unroll
        for (int qq = 0; qq < 16; qq++) p += wyx[qq] * pe[(size_t)qq * HID + o];
        g_h[(size_t)t * HID + o] = a + p;
    }
}

// ---------------- LN + adaLN modulate (fp16 output) ----------------
__global__ void __launch_bounds__(288) ln_mod_kernel(
    const float* __restrict__ sh, const float* __restrict__ sc, int mstride)
{
    int t = blockIdx.x;
    int b = t >> 8;
    int tid = threadIdx.x;
    const float* row = g_h + (size_t)t * HID;
    float v[4]; float s = 0.f, s2 = 0.f;
#pragma unroll
    for (int k = 0; k < 4; k++) {
        float xv = row[tid + k * 288];
        v[k] = xv; s += xv; s2 += xv * xv;
    }
#pragma unroll
    for (int o = 16; o > 0; o >>= 1) {
        s  += __shfl_xor_sync(0xffffffffu, s, o);
        s2 += __shfl_xor_sync(0xffffffffu, s2, o);
    }
    __shared__ float ws[9], ws2[9];
    int w = tid >> 5, lane = tid & 31;
    if (lane == 0) { ws[w] = s; ws2[w] = s2; }
    __syncthreads();
    if (tid == 0) {
        float a = 0.f, a2 = 0.f;
        for (int i = 0; i < 9; i++) { a += ws[i]; a2 += ws2[i]; }
        ws[0] = a; ws2[0] = a2;
    }
    __syncthreads();
    float mean = ws[0] * (1.f / HID);
    float var  = ws2[0] * (1.f / HID) - mean * mean;
    float rstd = rsqrtf(var + 1e-6f);
    const float* shr = sh + (size_t)b * mstride;
    const float* scr = sc + (size_t)b * mstride;
    __half* orow = g_x1h + (size_t)t * HID;
#pragma unroll
    for (int k = 0; k < 4; k++) {
        int j = tid + k * 288;
        float xm = (v[k] - mean) * rstd;
        orow[j] = __float2half(xm * (1.f + scr[j]) + shr[j]);
    }
}

// ---------------- neighborhood attention (fp16 qkv in, fp16 out) ----------------
__global__ void __launch_bounds__(256) attn_kernel()
{
    int t = blockIdx.x;
    int b = t >> 8, i = (t >> 4) & 15, j = t & 15;
    int tid = threadIdx.x;
    int h = tid >> 4, p = tid & 15;

    __shared__ int   ntok[16];
    __shared__ float att[16][16];

    if (tid < 16) {
        int py = tid >> 2, px = tid & 3;
        int si = min(max(i - 2, 0), 12);
        int sj = min(max(j - 2, 0), 12);
        ntok[tid] = (b << 8) | ((si + py) << 4) | (sj + px);
    }
    __syncthreads();

    const __half2* q2 = (const __half2*)(g_qkvh + (size_t)t * QKVN + h * DH);
    const __half2* k2 = (const __half2*)(g_qkvh + (size_t)ntok[p] * QKVN + HID + h * DH);
    float acc = 0.f;
#pragma unroll 6
    for (int d = 0; d < DH / 2; d++) {
        float2 qa = __half22float2(q2[d]);
        float2 kb = __half22float2(k2[d]);
        acc = fmaf(qa.x, kb.x, acc);
        acc = fmaf(qa.y, kb.y, acc);
    }
    acc *= 0.11785113019775793f;

    float m = acc;
#pragma unroll
    for (int o = 8; o > 0; o >>= 1) m = fmaxf(m, __shfl_xor_sync(0xffffffffu, m, o, 16));
    float e = expf(acc - m);
    float s = e;
#pragma unroll
    for (int o = 8; o > 0; o >>= 1) s += __shfl_xor_sync(0xffffffffu, s, o, 16);
    att[h][p] = e / s;
    __syncthreads();

    for (int o = tid; o < HID; o += 256) {
        int hh = o / DH;
        float sum = 0.f;
#pragma unroll
        for (int p2 = 0; p2 < 16; p2++)
            sum += att[hh][p2] * __half2float(g_qkvh[(size_t)ntok[p2] * QKVN + 2304 + o]);
        g_aoh[(size_t)t * HID + o] = __float2half(sum);
    }
}

// ---------------- final linear + unpatchify ----------------
__global__ void __launch_bounds__(256) final_kernel(
    const float* __restrict__ flw, const float* __restrict__ flb, float* __restrict__ out)
{
    int t = blockIdx.x;
    int b = t >> 8, gy = (t >> 4) & 15, gx = t & 15;
    __shared__ float xs[HID];
    __shared__ float part[8][32];
    int tid = threadIdx.x;
    for (int k = tid; k < HID; k += 256) xs[k] = __half2float(g_x1h[(size_t)t * HID + k]);
    __syncthreads();
    int col = tid & 31, seg = tid >> 5;
    float acc = 0.f;
    int k0 = seg * 144;
    for (int k = k0; k < k0 + 144; k++)
        acc += xs[k] * flw[(size_t)k * 32 + col];
    part[seg][col] = acc;
    __syncthreads();
    if (tid < 32) {
        float s = flb[tid];
#pragma unroll
        for (int sg = 0; sg < 8; sg++) s += part[sg][tid];
        int ch = tid & 7, pq = tid >> 3, p = pq >> 1, q = pq & 1;
        out[(((size_t)b * 8 + ch) * 32 + gy * 2 + p) * 32 + gx * 2 + q] = s;
    }
}

// ---------------- launch ----------------
extern "C" void kernel_launch(void* const* d_in, const int* in_sizes, int n_in,
                              void* d_out, int out_size)
{
    const float* x    = (const float*)d_in[0];
    const float* tin  = (const float*)d_in[1];
    const int*   y    = (const int*)  d_in[2];
    const float* pos  = (const float*)d_in[3];
    const float* pw   = (const float*)d_in[4];
    const float* pb   = (const float*)d_in[5];
    const float* tw1  = (const float*)d_in[6];
    const float* tb1  = (const float*)d_in[7];
    const float* tw2  = (const float*)d_in[8];
    const float* tb2  = (const float*)d_in[9];
    const float* ytab = (const float*)d_in[10];
    const float* adaw = (const float*)d_in[11];
    const float* adab = (const float*)d_in[12];
    const float* qkvw = (const float*)d_in[13];
    const float* qkvb = (const float*)d_in[14];
    const float* prjw = (const float*)d_in[15];
    const float* prjb = (const float*)d_in[16];
    const float* m1w  = (const float*)d_in[17];
    const float* m1b  = (const float*)d_in[18];
    const float* m2w  = (const float*)d_in[19];
    const float* m2b  = (const float*)d_in[20];
    const float* flaw = (const float*)d_in[21];
    const float* flab = (const float*)d_in[22];
    const float* flw  = (const float*)d_in[23];
    const float* flb  = (const float*)d_in[24];
    float* out = (float*)d_out;

    float *p_h, *p_mod, *p_fmod, *p_te, *p_e1, *p_scb;
    __half *p_qkvh, *p_x1h, *p_aoh, *p_mhh, *p_wh;
    cudaGetSymbolAddress((void**)&p_h,   g_h);
    cudaGetSymbolAddress((void**)&p_mod, g_mod);
    cudaGetSymbolAddress((void**)&p_fmod, g_fmod);
    cudaGetSymbolAddress((void**)&p_te,  g_te);
    cudaGetSymbolAddress((void**)&p_e1,  g_e1);
    cudaGetSymbolAddress((void**)&p_scb, g_scb);
    cudaGetSymbolAddress((void**)&p_qkvh, g_qkvh);
    cudaGetSymbolAddress((void**)&p_x1h, g_x1h);
    cudaGetSymbolAddress((void**)&p_aoh, g_aoh);
    cudaGetSymbolAddress((void**)&p_mhh, g_mhh);
    cudaGetSymbolAddress((void**)&p_wh,  g_wh);

    cudaFuncSetAttribute(mma_gemm<0>, cudaFuncAttributeMaxDynamicSharedMemorySize, GSME);
    cudaFuncSetAttribute(mma_gemm<1>, cudaFuncAttributeMaxDynamicSharedMemorySize, GSME);
    cudaFuncSetAttribute(mma_gemm<2>, cudaFuncAttributeMaxDynamicSharedMemorySize, GSME);

    // weight fp16 mirrors
    for (int l = 0; l < 2; l++) {
        w2h_kernel<<<HID * QKVN / 1024, 256>>>(qkvw + (size_t)l * HID * QKVN, p_wh + (size_t)l * LSZ + OFF_QKV, HID * QKVN);
        w2h_kernel<<<HID * HID  / 1024, 256>>>(prjw + (size_t)l * HID * HID,  p_wh + (size_t)l * LSZ + OFF_PROJ, HID * HID);
        w2h_kernel<<<HID * MLPN / 1024, 256>>>(m1w  + (size_t)l * HID * MLPN, p_wh + (size_t)l * LSZ + OFF_M1, HID * MLPN);
        w2h_kernel<<<MLPN * HID / 1024, 256>>>(m2w  + (size_t)l * MLPN * HID, p_wh + (size_t)l * LSZ + OFF_M2, MLPN * HID);
    }

    patchify_kernel<<<TOK, 288>>>(x, pw, pb, pos);

    // conditioning path
    te_kernel<<<BATCH, 256>>>(tin);
    smk_part<<<dim3(HID / 128, 2), 128>>>(p_te, tw1, HID);
    smk_reduce<1><<<dim3(HID / 128, BATCH), 128>>>(tb1, nullptr, nullptr, p_e1, HID, 2);
    smk_part<<<dim3(HID / 128, 9), 128>>>(p_e1, tw2, HID);
    smk_reduce<2><<<dim3(HID / 128, BATCH), 128>>>(tb2, ytab, y, p_scb, HID, 9);

    for (int l = 0; l < 2; l++) {
        const __half* whL = p_wh + (size_t)l * LSZ;
        const float* ab = adab + (size_t)l * ADAN;
        smk_part<<<dim3(ADAN / 128, 9), 128>>>(p_scb, adaw + (size_t)l * HID * ADAN, ADAN);
        smk_reduce<0><<<dim3(ADAN / 128, BATCH), 128>>>(ab, nullptr, nullptr, p_mod, ADAN, 9);

        // attention block
        ln_mod_kernel<<<TOK, 288>>>(p_mod + 0, p_mod + HID, ADAN);
        mma_gemm<0><<<dim3(QKVN / 128, TOK / 128), 256, GSME>>>(
            p_x1h, whL + OFF_QKV, qkvb + (size_t)l * QKVN, p_qkvh, nullptr, 0, QKVN, HID);
        attn_kernel<<<TOK, 256>>>();
        mma_gemm<2><<<dim3(HID / 128, TOK / 128), 256, GSME>>>(
            p_aoh, whL + OFF_PROJ, prjb + (size_t)l * HID, p_h, p_mod + 2 * HID, ADAN, HID, HID);

        // mlp block
        ln_mod_kernel<<<TOK, 288>>>(p_mod + 3 * HID, p_mod + 4 * HID, ADAN);
        mma_gemm<1><<<dim3(MLPN / 128, TOK / 128), 256, GSME>>>(
            p_x1h, whL + OFF_M1, m1b + (size_t)l * MLPN, p_mhh, nullptr, 0, MLPN, HID);
        mma_gemm<2><<<dim3(HID / 128, TOK / 128), 256, GSME>>>(
            p_mhh, whL + OFF_M2, m2b + (size_t)l * HID, p_h, p_mod + 5 * HID, ADAN, HID, MLPN);
    }

    smk_part<<<dim3(2304 / 128, 9), 128>>>(p_scb, flaw, 2304);
    smk_reduce<0><<<dim3(2304 / 128, BATCH), 128>>>(flab, nullptr, nullptr, p_fmod, 2304, 9);
    ln_mod_kernel<<<TOK, 288>>>(p_fmod + 0, p_fmod + HID, 2304);
    final_kernel<<<TOK, 256>>>(flw, flb, out);

    (void)in_sizes; (void)n_in; (void)out_size;
}